// round 6
// baseline (speedup 1.0000x reference)
#include <cuda_runtime.h>
#include <math.h>

#define NC    10
#define NG    8
#define TPB   256
#define POOLQ 256                 // int4 labels per k_bucket block
#define POOL  (POOLQ * 4)         // 1024 labels -> pool entries
#define MAXN  500000
#define B2    40                  // blocks per class in k_gather
#define GRID2 (NC * B2)

// Scratch (__device__ globals; zero-init at load, finalize resets for replays)
__device__ int      g_idx[NC][MAXN];   // per-class row-index lists
__device__ int      g_cnt[NC];
__device__ float    g_S[NC * NG];
__device__ float    g_V[NC * NG];
__device__ unsigned g_ticket;

// ---------------------------------------------------------------------------
// k_bucket: single label scan -> per-class index lists.
// Two-phase shared staging (count, then place), warp-aggregated shared atomics
// via __match_any_sync, one global reserve per class per block, coalesced copy.
__global__ __launch_bounds__(TPB) void k_bucket(const int* __restrict__ labels,
                                                int N) {
    const int nq = N >> 2;
    const int q0 = blockIdx.x * POOLQ;
    const int q1 = min(nq, q0 + POOLQ);
    const int w    = threadIdx.x >> 5;
    const int lane = threadIdx.x & 31;
    const unsigned ltmask = (1u << lane) - 1u;

    __shared__ int s_cnt[NC], s_off[NC], s_place[NC], s_base[NC];
    __shared__ int s_pool[POOL];

    if (threadIdx.x < NC) { s_cnt[threadIdx.x] = 0; s_place[threadIdx.x] = 0; }
    __syncthreads();

    const int4* lab4 = (const int4*)labels;
    const bool tailB = (blockIdx.x == gridDim.x - 1) && ((N & 3) != 0);

    // ---- phase 1: count (warp-uniform loops; all 32 lanes in every sync op)
    #define CNT1(CC) {                                                          \
        int cc_ = (CC);                                                         \
        unsigned m = __match_any_sync(0xFFFFFFFFu, cc_);                        \
        if ((unsigned)cc_ < NC && lane == __ffs(m) - 1)                         \
            atomicAdd(&s_cnt[cc_], __popc(m)); }
    for (int base = q0 + w * 32; base < q1; base += (TPB / 32) * 32) {
        int q = base + lane;
        int4 lb = make_int4(0, 0, 0, 0);
        if (q < q1) lb = lab4[q];
        CNT1(lb.x - 1) CNT1(lb.y - 1) CNT1(lb.z - 1) CNT1(lb.w - 1)
    }
    if (tailB && w == 0) {
        for (int nb = nq << 2; nb < N; nb += 32) {
            int n = nb + lane;
            int lv = (n < N) ? labels[n] : 0;
            CNT1(lv - 1)
        }
    }
    #undef CNT1
    __syncthreads();

    if (threadIdx.x == 0) {
        int acc = 0;
        #pragma unroll
        for (int c = 0; c < NC; ++c) { s_off[c] = acc; acc += s_cnt[c]; }
    }
    if (threadIdx.x < NC)
        s_base[threadIdx.x] = atomicAdd(&g_cnt[threadIdx.x], s_cnt[threadIdx.x]);
    __syncthreads();

    // ---- phase 2: place
    #define PUT(CC, NN) {                                                       \
        int cc_ = (CC);                                                         \
        unsigned m = __match_any_sync(0xFFFFFFFFu, cc_);                        \
        int ldr = __ffs(m) - 1;                                                 \
        int bpos = 0;                                                           \
        if ((unsigned)cc_ < NC && lane == ldr)                                  \
            bpos = atomicAdd(&s_place[cc_], __popc(m));                         \
        bpos = __shfl_sync(0xFFFFFFFFu, bpos, ldr);                             \
        if ((unsigned)cc_ < NC)                                                 \
            s_pool[s_off[cc_] + bpos + __popc(m & ltmask)] = (NN); }
    for (int base = q0 + w * 32; base < q1; base += (TPB / 32) * 32) {
        int q = base + lane;
        int4 lb = make_int4(0, 0, 0, 0);
        if (q < q1) lb = lab4[q];
        int n = q << 2;
        PUT(lb.x - 1, n) PUT(lb.y - 1, n + 1) PUT(lb.z - 1, n + 2) PUT(lb.w - 1, n + 3)
    }
    if (tailB && w == 0) {
        for (int nb = nq << 2; nb < N; nb += 32) {
            int n = nb + lane;
            int lv = (n < N) ? labels[n] : 0;
            PUT(lv - 1, n)
        }
    }
    #undef PUT
    __syncthreads();

    // ---- coalesced copy to global per-class lists
    for (int c = 0; c < NC; ++c) {
        int cnt = s_cnt[c], gb = s_base[c], so = s_off[c];
        for (int i = threadIdx.x; i < cnt; i += TPB)
            g_idx[c][gb + i] = s_pool[so + i];
    }
}

// ---------------------------------------------------------------------------
// Per-row accumulate: S_i += a_i;  V_i += a_i * (R - log a_i), R = sum log a_j
#define ACC(AQ, BQ)                                                             \
    {                                                                           \
        float a[NG] = {(AQ).x, (AQ).y, (AQ).z, (AQ).w,                          \
                       (BQ).x, (BQ).y, (BQ).z, (BQ).w};                         \
        float la[NG]; float R = 0.0f;                                           \
        _Pragma("unroll")                                                       \
        for (int g = 0; g < NG; ++g) { la[g] = __logf(a[g]); R += la[g]; }      \
        _Pragma("unroll")                                                       \
        for (int g = 0; g < NG; ++g) {                                          \
            s[g] += a[g];                                                       \
            v[g] = fmaf(a[g], R - la[g], v[g]);                                 \
        }                                                                       \
    }

// ---------------------------------------------------------------------------
// k_gather: balanced gather + accumulate over per-class lists; last-block
// ticket finalize computes the scalar and resets scratch for the next replay.
__global__ __launch_bounds__(TPB) void k_gather(const float* __restrict__ act,
                                                int N, float* __restrict__ out) {
    const int cc = blockIdx.x / B2;
    const int b  = blockIdx.x % B2;
    const size_t clsBase = (size_t)cc * (size_t)N;
    const int cnt = __ldcg(&g_cnt[cc]);
    const int* __restrict__ lst = g_idx[cc];
    const int stride = B2 * TPB;

    float s[NG] = {0,0,0,0,0,0,0,0};
    float v[NG] = {0,0,0,0,0,0,0,0};

    int i = b * TPB + threadIdx.x;

    // unroll-4: hoist all loads (4 idx + 8x16B rows) for MLP, then compute
    while (i + 3 * stride < cnt) {
        int n0 = __ldg(lst + i);
        int n1 = __ldg(lst + i + stride);
        int n2 = __ldg(lst + i + 2 * stride);
        int n3 = __ldg(lst + i + 3 * stride);
        const float4* p0 = (const float4*)(act + (clsBase + (size_t)n0) * NG);
        const float4* p1 = (const float4*)(act + (clsBase + (size_t)n1) * NG);
        const float4* p2 = (const float4*)(act + (clsBase + (size_t)n2) * NG);
        const float4* p3 = (const float4*)(act + (clsBase + (size_t)n3) * NG);
        float4 x0 = p0[0], y0 = p0[1];
        float4 x1 = p1[0], y1 = p1[1];
        float4 x2 = p2[0], y2 = p2[1];
        float4 x3 = p3[0], y3 = p3[1];
        ACC(x0, y0) ACC(x1, y1) ACC(x2, y2) ACC(x3, y3)
        i += 4 * stride;
    }
    for (; i < cnt; i += stride) {
        int n = __ldg(lst + i);
        const float4* p = (const float4*)(act + (clsBase + (size_t)n) * NG);
        float4 xq = p[0], yq = p[1];
        ACC(xq, yq)
    }

    // warp tree-reduce 16 values (all threads converged here)
    #pragma unroll
    for (int o = 16; o > 0; o >>= 1) {
        #pragma unroll
        for (int g = 0; g < NG; ++g) {
            s[g] += __shfl_down_sync(0xFFFFFFFFu, s[g], o);
            v[g] += __shfl_down_sync(0xFFFFFFFFu, v[g], o);
        }
    }

    __shared__ float sh[2 * NG];
    __shared__ bool amLast;
    __shared__ float pc[NC];
    if (threadIdx.x < 2 * NG) sh[threadIdx.x] = 0.0f;
    __syncthreads();
    if ((threadIdx.x & 31) == 0) {
        #pragma unroll
        for (int g = 0; g < NG; ++g) {
            atomicAdd(&sh[g], s[g]);
            atomicAdd(&sh[NG + g], v[g]);
        }
    }
    __syncthreads();
    if (threadIdx.x < NG) {
        atomicAdd(&g_S[cc * NG + threadIdx.x], sh[threadIdx.x]);
        atomicAdd(&g_V[cc * NG + threadIdx.x], sh[NG + threadIdx.x]);
    }

    // ---- last-block finalize ----
    __threadfence();
    if (threadIdx.x == 0)
        amLast = (atomicAdd(&g_ticket, 1u) == (unsigned)(GRID2 - 1));
    __syncthreads();
    if (!amLast) return;

    int t = threadIdx.x;
    if (t < NC) pc[t] = 0.0f;
    __syncthreads();
    if (t < NC * NG) {
        float S = __ldcg(&g_S[t]);
        float V = __ldcg(&g_V[t]);
        float term = V / S - (float)(NG - 1) * logf(S);
        atomicAdd(&pc[t / NG], term);
    }
    __syncthreads();
    if (t == 0) {
        float num = 0.0f, vcnt = 0.0f;
        #pragma unroll
        for (int c = 0; c < NC; ++c) {
            int cn = __ldcg(&g_cnt[c]);
            if (cn >= 2) { num += pc[c]; vcnt += 1.0f; }
        }
        out[0] = num / (vcnt * (float)(NG * (NG - 1)));
        g_ticket = 0;                         // reset for next replay
    }
    __syncthreads();
    if (t < NC * NG) { g_S[t] = 0.0f; g_V[t] = 0.0f; }
    if (t < NC) g_cnt[t] = 0;
}

// ---------------------------------------------------------------------------
extern "C" void kernel_launch(void* const* d_in, const int* in_sizes, int n_in,
                              void* d_out, int out_size) {
    const float* act  = (const float*)d_in[0];   // [C, N, G] float32
    const int* labels = (const int*)d_in[1];     // [N] int32
    const int N = in_sizes[1];

    int nq = N >> 2;
    int grid1 = (nq + POOLQ - 1) / POOLQ;
    if (grid1 < 1) grid1 = 1;

    k_bucket<<<grid1, TPB>>>(labels, N);
    k_gather<<<GRID2, TPB>>>(act, N, (float*)d_out);
}